// round 12
// baseline (speedup 1.0000x reference)
#include <cuda_runtime.h>
#include <cuda_fp16.h>
#include <cstdint>

#define N_NODES 100000
#define N_EDGES 1600000
#define N_GRAPHS 64

// ---------------- device scratch (allocations forbidden) ----------------
__device__ __align__(16) __half g_aggh[(size_t)N_NODES * 128];  // 25.6 MB, fp16 accumulators
__device__ float g_ugb[N_GRAPHS * 256];                   // b1 + u@W1u per graph
__device__ __align__(16) __half g_W1t[256 * 256];         // W1[0:256]^T fp16, [n][k]
__device__ __align__(16) __half g_W2t[128 * 256];         // W2^T fp16, [n][k]

// ---------------- helpers ----------------
__device__ __forceinline__ void mma16(float* c, const unsigned* a, unsigned b0, unsigned b1) {
    asm volatile(
        "mma.sync.aligned.m16n8k16.row.col.f32.f16.f16.f32 "
        "{%0,%1,%2,%3}, {%4,%5,%6,%7}, {%8,%9}, {%0,%1,%2,%3};"
        : "+f"(c[0]), "+f"(c[1]), "+f"(c[2]), "+f"(c[3])
        : "r"(a[0]), "r"(a[1]), "r"(a[2]), "r"(a[3]), "r"(b0), "r"(b1));
}

__device__ __forceinline__ void cp16(void* dst_smem, const void* src) {
    unsigned d = (unsigned)__cvta_generic_to_shared(dst_smem);
    asm volatile("cp.async.ca.shared.global [%0], [%1], 16;" :: "r"(d), "l"(src) : "memory");
}
#define CP_COMMIT() asm volatile("cp.async.commit_group;" ::: "memory")
#define CP_WAIT(n)  asm volatile("cp.async.wait_group %0;" :: "n"(n) : "memory")

__device__ __forceinline__ unsigned pack2(float a, float b) {
    __half2 h = __floats2half2_rn(a, b);
    return *(unsigned*)&h;
}

__device__ __forceinline__ void red_v4_f16x2(__half* dst, unsigned r0, unsigned r1,
                                             unsigned r2, unsigned r3) {
    asm volatile("red.global.add.noftz.v4.f16x2 [%0], {%1, %2, %3, %4};"
                 :: "l"(dst), "r"(r0), "r"(r1), "r"(r2), "r"(r3) : "memory");
}

// ---------------- merged prep: W1^T fp16 | W2^T fp16 | ugb ----------------
__global__ void prep_kernel(const float* __restrict__ W1, const float* __restrict__ W2,
                            const float* __restrict__ u, const float* __restrict__ b1) {
    int bid = blockIdx.x;
    if (bid < 256) {
        int idx = bid * 256 + threadIdx.x;
        int n = idx >> 8, k = idx & 255;
        g_W1t[n * 256 + k] = __float2half_rn(W1[k * 256 + n]);
    } else if (bid < 384) {
        int idx = (bid - 256) * 256 + threadIdx.x;
        int n = idx >> 8, k = idx & 255;
        g_W2t[n * 256 + k] = __float2half_rn(W2[k * 128 + n]);
    } else {
        int g = bid - 384, n = threadIdx.x;
        float acc = b1[n];
#pragma unroll
        for (int j = 0; j < 16; j++) acc += u[g * 16 + j] * W1[(256 + j) * 256 + n];
        g_ugb[g * 256 + n] = acc;
    }
}

// ---------------- edge scatter: fp16 v4.f16x2 RED, 4 edges/half-warp, MLP=8 ----------------
// Warp handles 8 edges. Half-warp hw handles edges [w*8 + hw*4, +4).
// Lane l (0..15) owns bytes [l*32, l*32+32) of each 512B edge row.
__global__ void scatter_kernel(const float* __restrict__ ea, const int* __restrict__ col) {
    int w  = blockIdx.x * 8 + (threadIdx.x >> 5);
    int hw = (threadIdx.x >> 4) & 1;
    int l  = threadIdx.x & 15;
    int eb = w * 8 + hw * 4;

    int c0 = __ldg(col + eb);
    int c1 = __ldg(col + eb + 1);
    int c2 = __ldg(col + eb + 2);
    int c3 = __ldg(col + eb + 3);

    const float4* p = (const float4*)(ea + (size_t)eb * 128) + 2 * l;
    // all 8 independent loads issued before any consumer (MLP=8)
    float4 a0 = __ldcs(p);        float4 a1 = __ldcs(p + 1);
    float4 b0 = __ldcs(p + 32);   float4 b1 = __ldcs(p + 33);
    float4 d0 = __ldcs(p + 64);   float4 d1 = __ldcs(p + 65);
    float4 f0 = __ldcs(p + 96);   float4 f1 = __ldcs(p + 97);

    __half* dst = g_aggh + l * 8;
    if ((unsigned)c0 < N_NODES)
        red_v4_f16x2(dst + (size_t)c0 * 128, pack2(a0.x, a0.y), pack2(a0.z, a0.w),
                                             pack2(a1.x, a1.y), pack2(a1.z, a1.w));
    if ((unsigned)c1 < N_NODES)
        red_v4_f16x2(dst + (size_t)c1 * 128, pack2(b0.x, b0.y), pack2(b0.z, b0.w),
                                             pack2(b1.x, b1.y), pack2(b1.z, b1.w));
    if ((unsigned)c2 < N_NODES)
        red_v4_f16x2(dst + (size_t)c2 * 128, pack2(d0.x, d0.y), pack2(d0.z, d0.w),
                                             pack2(d1.x, d1.y), pack2(d1.z, d1.w));
    if ((unsigned)c3 < N_NODES)
        red_v4_f16x2(dst + (size_t)c3 * 128, pack2(f0.x, f0.y), pack2(f0.z, f0.w),
                                             pack2(f1.x, f1.y), pack2(f1.z, f1.w));
}

// ---------------- fused 2-layer MLP (fp16 mma, 512 threads/16 warps) — unchanged ----------------
#define HS2 132
#define WSB 20
#define HS_BYTES (128 * HS2 * 4)
#define B1BUF (256 * WSB)
#define B2BUF (128 * WSB)
#define WSL_BYTES (2 * B1BUF * 4)
#define SMEM_TOTAL (HS_BYTES + WSL_BYTES + 1024)

__global__ void __launch_bounds__(512, 1) mlp_kernel(
    const float* __restrict__ x, const int* __restrict__ batch,
    const float* __restrict__ b2, float* __restrict__ out)
{
    extern __shared__ unsigned char sm[];
    unsigned* hs  = (unsigned*)sm;
    unsigned* wsl = (unsigned*)(sm + HS_BYTES);
    int*      gb  = (int*)(sm + HS_BYTES + WSL_BYTES);
    float*    b2s = (float*)(sm + HS_BYTES + WSL_BYTES + 512);

    const int tid  = threadIdx.x;
    const int wid  = tid >> 5;
    const int lane = tid & 31;
    const int g    = lane >> 2;
    const int t    = lane & 3;
    const int base = blockIdx.x * 128;
    const int wm   = (wid >> 2) * 32;
    const int wn   = (wid & 3) * 64;

    {
#pragma unroll
        for (int i = 0; i < 2; i++) {
            int q = tid + i * 512;
            int n = q >> 2, j = q & 3;
            cp16((char*)wsl + n * 80 + j * 16, (const char*)g_W1t + n * 512 + j * 16);
        }
        CP_COMMIT();
    }

    if (tid < 128) {
        int node = min(base + tid, N_NODES - 1);
        int gv = batch[node];
        gb[tid]  = min(max(gv, 0), N_GRAPHS - 1);
        b2s[tid] = b2[tid];
    }

    // fill hs: cols 0-127 = fp16(x), cols 128-255 = g_aggh (already fp16)
#pragma unroll
    for (int i = 0; i < 16; i++) {
        int uq = tid + i * 512;
        int r = uq >> 6, c4 = (uq & 63) << 2;
        int node = base + r;
        uint2 o = make_uint2(0u, 0u);
        if (node < N_NODES) {
            if (c4 < 128) {
                float4 v = __ldg((const float4*)(x + (size_t)node * 128 + c4));
                o.x = pack2(v.x, v.y);
                o.y = pack2(v.z, v.w);
            } else {
                o = __ldg((const uint2*)(g_aggh + (size_t)node * 128 + (c4 - 128)));
            }
        }
        *(uint2*)(hs + r * HS2 + (c4 >> 1)) = o;
    }

    float acc[2][8][4];
#pragma unroll
    for (int a = 0; a < 2; a++)
#pragma unroll
        for (int b = 0; b < 8; b++)
#pragma unroll
            for (int q = 0; q < 4; q++) acc[a][b][q] = 0.f;

#pragma unroll 1
    for (int c = 0; c < 8; c++) {
        if (c < 7) {
            unsigned* dst = wsl + ((c + 1) & 1) * B1BUF;
            const char* src = (const char*)g_W1t + (c + 1) * 64;
#pragma unroll
            for (int i = 0; i < 2; i++) {
                int q = tid + i * 512;
                int n = q >> 2, j = q & 3;
                cp16((char*)dst + n * 80 + j * 16, src + n * 512 + j * 16);
            }
            CP_COMMIT(); CP_WAIT(1);
        } else {
            CP_WAIT(0);
        }
        __syncthreads();
        const unsigned* wb = wsl + (c & 1) * B1BUF;
#pragma unroll
        for (int ks = 0; ks < 2; ks++) {
            const int kg2 = c * 16 + ks * 8;
            const int kb2 = ks * 8;
            unsigned a_[2][4];
#pragma unroll
            for (int mf = 0; mf < 2; mf++) {
                int r0 = (wm + mf * 16 + g) * HS2;
                int r1 = r0 + 8 * HS2;
                a_[mf][0] = hs[r0 + kg2 + t];
                a_[mf][1] = hs[r1 + kg2 + t];
                a_[mf][2] = hs[r0 + kg2 + t + 4];
                a_[mf][3] = hs[r1 + kg2 + t + 4];
            }
#pragma unroll
            for (int nf = 0; nf < 8; nf++) {
                int n = wn + nf * 8 + g;
                unsigned b0 = wb[n * WSB + kb2 + t];
                unsigned b1 = wb[n * WSB + kb2 + t + 4];
#pragma unroll
                for (int mf = 0; mf < 2; mf++)
                    mma16(acc[mf][nf], a_[mf], b0, b1);
            }
        }
        __syncthreads();
    }

    {
        int n = tid >> 2, j = tid & 3;
        cp16((char*)wsl + n * 80 + j * 16, (const char*)g_W2t + n * 512 + j * 16);
        CP_COMMIT();
    }

#pragma unroll
    for (int mf = 0; mf < 2; mf++) {
        int r0 = wm + mf * 16 + g;
        int r1 = r0 + 8;
        const float* u0 = g_ugb + gb[r0] * 256;
        const float* u1 = g_ugb + gb[r1] * 256;
#pragma unroll
        for (int nf = 0; nf < 8; nf++) {
            int n0 = wn + nf * 8 + 2 * t;
            float f0 = fmaxf(acc[mf][nf][0] + u0[n0], 0.f);
            float f1 = fmaxf(acc[mf][nf][1] + u0[n0 + 1], 0.f);
            float f2 = fmaxf(acc[mf][nf][2] + u1[n0], 0.f);
            float f3 = fmaxf(acc[mf][nf][3] + u1[n0 + 1], 0.f);
            hs[r0 * HS2 + (n0 >> 1)] = pack2(f0, f1);
            hs[r1 * HS2 + (n0 >> 1)] = pack2(f2, f3);
        }
    }
    __syncthreads();

    const int wn2 = (wid & 3) * 32;
    float acc2[2][4][4];
#pragma unroll
    for (int a = 0; a < 2; a++)
#pragma unroll
        for (int b = 0; b < 4; b++)
#pragma unroll
            for (int q = 0; q < 4; q++) acc2[a][b][q] = 0.f;

#pragma unroll 1
    for (int c = 0; c < 8; c++) {
        if (c < 7) {
            unsigned* dst = wsl + ((c + 1) & 1) * B2BUF;
            const char* src = (const char*)g_W2t + (c + 1) * 64;
            {
                int q = tid;
                int n = q >> 2, j = q & 3;
                cp16((char*)dst + n * 80 + j * 16, src + n * 512 + j * 16);
            }
            CP_COMMIT(); CP_WAIT(1);
        } else {
            CP_WAIT(0);
        }
        __syncthreads();
        const unsigned* wb = wsl + (c & 1) * B2BUF;
#pragma unroll
        for (int ks = 0; ks < 2; ks++) {
            const int kg2 = c * 16 + ks * 8;
            const int kb2 = ks * 8;
            unsigned a_[2][4];
#pragma unroll
            for (int mf = 0; mf < 2; mf++) {
                int r0 = (wm + mf * 16 + g) * HS2;
                int r1 = r0 + 8 * HS2;
                a_[mf][0] = hs[r0 + kg2 + t];
                a_[mf][1] = hs[r1 + kg2 + t];
                a_[mf][2] = hs[r0 + kg2 + t + 4];
                a_[mf][3] = hs[r1 + kg2 + t + 4];
            }
#pragma unroll
            for (int nf = 0; nf < 4; nf++) {
                int n = wn2 + nf * 8 + g;
                unsigned b0 = wb[n * WSB + kb2 + t];
                unsigned b1 = wb[n * WSB + kb2 + t + 4];
#pragma unroll
                for (int mf = 0; mf < 2; mf++)
                    mma16(acc2[mf][nf], a_[mf], b0, b1);
            }
        }
        __syncthreads();
    }

#pragma unroll
    for (int mf = 0; mf < 2; mf++) {
        int r0 = wm + mf * 16 + g;
        int r1 = r0 + 8;
        int node0 = base + r0;
        int node1 = base + r1;
#pragma unroll
        for (int nf = 0; nf < 4; nf++) {
            int col = wn2 + nf * 8 + 2 * t;
            if (node0 < N_NODES) {
                float2 xv = *(const float2*)(x + (size_t)node0 * 128 + col);
                float2 o;
                o.x = acc2[mf][nf][0] + b2s[col] + xv.x;
                o.y = acc2[mf][nf][1] + b2s[col + 1] + xv.y;
                *(float2*)(out + (size_t)node0 * 128 + col) = o;
            }
            if (node1 < N_NODES) {
                float2 xv = *(const float2*)(x + (size_t)node1 * 128 + col);
                float2 o;
                o.x = acc2[mf][nf][2] + b2s[col] + xv.x;
                o.y = acc2[mf][nf][3] + b2s[col + 1] + xv.y;
                *(float2*)(out + (size_t)node1 * 128 + col) = o;
            }
        }
    }
}

// ---------------- launch (prep forked onto side stream under memset) ----------------
extern "C" void kernel_launch(void* const* d_in, const int* in_sizes, int n_in,
                              void* d_out, int out_size) {
    const float* x = nullptr; const int* edge_index = nullptr; const float* edge_attr = nullptr;
    const float* u = nullptr; const int* batch = nullptr;
    const float* W1 = nullptr; const float* b1 = nullptr;
    const float* W2 = nullptr; const float* b2 = nullptr;

    for (int i = 0; i < n_in; i++) {
        switch (in_sizes[i]) {
            case 12800000:  x          = (const float*)d_in[i]; break;
            case 3200000:   edge_index = (const int*)d_in[i];   break;
            case 204800000: edge_attr  = (const float*)d_in[i]; break;
            case 1024:      u          = (const float*)d_in[i]; break;
            case 100000:    batch      = (const int*)d_in[i];   break;
            case 69632:     W1         = (const float*)d_in[i]; break;
            case 256:       b1         = (const float*)d_in[i]; break;
            case 32768:     W2         = (const float*)d_in[i]; break;
            case 128:       b2         = (const float*)d_in[i]; break;
            default: break;
        }
    }
    float* out = (float*)d_out;
    const int* col = edge_index + N_EDGES;

    cudaFuncSetAttribute(mlp_kernel, cudaFuncAttributeMaxDynamicSharedMemorySize, SMEM_TOTAL);

    void* agg_ptr = nullptr;
    cudaGetSymbolAddress(&agg_ptr, g_aggh);

    // bounded leak: kernel_launch runs only a handful of times
    cudaStream_t s2;
    cudaStreamCreateWithFlags(&s2, cudaStreamNonBlocking);
    cudaEvent_t e0, e2;
    cudaEventCreateWithFlags(&e0, cudaEventDisableTiming);
    cudaEventCreateWithFlags(&e2, cudaEventDisableTiming);

    cudaEventRecord(e0, 0);
    cudaStreamWaitEvent(s2, e0, 0);
    prep_kernel<<<448, 256, 0, s2>>>(W1, W2, u, b1);          // hides under memset
    cudaEventRecord(e2, s2);

    cudaMemsetAsync(agg_ptr, 0, (size_t)N_NODES * 128 * sizeof(__half));
    scatter_kernel<<<N_EDGES / 64, 256>>>(edge_attr, col);

    cudaStreamWaitEvent(0, e2, 0);
    mlp_kernel<<<(N_NODES + 127) / 128, 512, SMEM_TOTAL>>>(x, batch, b2, out);
}

// round 16
// speedup vs baseline: 1.0321x; 1.0321x over previous
#include <cuda_runtime.h>
#include <cuda_fp16.h>
#include <cstdint>

#define N_NODES 100000
#define N_EDGES 1600000
#define N_GRAPHS 64

// ---------------- device scratch (allocations forbidden) ----------------
__device__ __align__(16) __half g_aggh[(size_t)N_NODES * 128];   // 25.6 MB fp16 accumulators
__device__ __align__(16) __half g_acc1h[(size_t)N_NODES * 256];  // 51.2 MB fp16: x@W1x + ugb
__device__ float g_ugb[N_GRAPHS * 256];
__device__ __align__(16) __half g_W1t[256 * 256];                // W1[0:256]^T fp16, [n][k]
__device__ __align__(16) __half g_W2t[128 * 256];                // W2^T fp16, [n][k]

// ---------------- helpers ----------------
__device__ __forceinline__ void mma16(float* c, const unsigned* a, unsigned b0, unsigned b1) {
    asm volatile(
        "mma.sync.aligned.m16n8k16.row.col.f32.f16.f16.f32 "
        "{%0,%1,%2,%3}, {%4,%5,%6,%7}, {%8,%9}, {%0,%1,%2,%3};"
        : "+f"(c[0]), "+f"(c[1]), "+f"(c[2]), "+f"(c[3])
        : "r"(a[0]), "r"(a[1]), "r"(a[2]), "r"(a[3]), "r"(b0), "r"(b1));
}

__device__ __forceinline__ void cp16(void* dst_smem, const void* src) {
    unsigned d = (unsigned)__cvta_generic_to_shared(dst_smem);
    asm volatile("cp.async.ca.shared.global [%0], [%1], 16;" :: "r"(d), "l"(src) : "memory");
}
#define CP_COMMIT() asm volatile("cp.async.commit_group;" ::: "memory")
#define CP_WAIT(n)  asm volatile("cp.async.wait_group %0;" :: "n"(n) : "memory")

__device__ __forceinline__ unsigned pack2(float a, float b) {
    __half2 h = __floats2half2_rn(a, b);
    return *(unsigned*)&h;
}

__device__ __forceinline__ void red_v4_f16x2(__half* dst, unsigned r0, unsigned r1,
                                             unsigned r2, unsigned r3) {
    asm volatile("red.global.add.noftz.v4.f16x2 [%0], {%1, %2, %3, %4};"
                 :: "l"(dst), "r"(r0), "r"(r1), "r"(r2), "r"(r3) : "memory");
}

// ---------------- prep: W1^T fp16 | W2^T fp16 | ugb ----------------
__global__ void prep_kernel(const float* __restrict__ W1, const float* __restrict__ W2,
                            const float* __restrict__ u, const float* __restrict__ b1) {
    int bid = blockIdx.x;
    if (bid < 256) {
        int idx = bid * 256 + threadIdx.x;
        int n = idx >> 8, k = idx & 255;
        g_W1t[n * 256 + k] = __float2half_rn(W1[k * 256 + n]);
    } else if (bid < 384) {
        int idx = (bid - 256) * 256 + threadIdx.x;
        int n = idx >> 8, k = idx & 255;
        g_W2t[n * 256 + k] = __float2half_rn(W2[k * 128 + n]);
    } else {
        int g = bid - 384, n = threadIdx.x;
        float acc = b1[n];
#pragma unroll
        for (int j = 0; j < 16; j++) acc += u[g * 16 + j] * W1[(256 + j) * 256 + n];
        g_ugb[g * 256 + n] = acc;
    }
}

// ---------------- edge scatter: R11 exact (4 edges/warp; launch with N_EDGES/32) ----------------
__global__ void scatter_kernel(const float* __restrict__ ea, const int* __restrict__ col) {
    int w  = blockIdx.x * 8 + (threadIdx.x >> 5);
    int hw = (threadIdx.x >> 4) & 1;
    int l  = threadIdx.x & 15;
    int e0 = w * 4 + hw;
    int e1 = e0 + 2;
    int c0 = __ldg(col + e0);
    int c1 = __ldg(col + e1);
    const float4* p0 = (const float4*)(ea + (size_t)e0 * 128) + 2 * l;
    const float4* p1 = (const float4*)(ea + (size_t)e1 * 128) + 2 * l;
    float4 a0 = __ldcs(p0);
    float4 a1 = __ldcs(p0 + 1);
    float4 b0 = __ldcs(p1);
    float4 b1 = __ldcs(p1 + 1);
    unsigned r0 = pack2(a0.x, a0.y), r1 = pack2(a0.z, a0.w);
    unsigned r2 = pack2(a1.x, a1.y), r3 = pack2(a1.z, a1.w);
    unsigned s0 = pack2(b0.x, b0.y), s1 = pack2(b0.z, b0.w);
    unsigned s2 = pack2(b1.x, b1.y), s3 = pack2(b1.z, b1.w);
    if ((unsigned)c0 < N_NODES) red_v4_f16x2(g_aggh + (size_t)c0 * 128 + l * 8, r0, r1, r2, r3);
    if ((unsigned)c1 < N_NODES) red_v4_f16x2(g_aggh + (size_t)c1 * 128 + l * 8, s0, s1, s2, s3);
}

// ---------------- tiling constants ----------------
#define HS2 132                      // mlp_b hs row stride (half2)
#define HS2A 68                      // mlp_a hs row stride (half2)
#define WSB 20
#define B1BUF (256 * WSB)
#define B2BUF (128 * WSB)
#define WSL_BYTES (2 * B1BUF * 4)    // 40960
#define HSA_BYTES (128 * HS2A * 4)   // 34816
#define HS_BYTES (128 * HS2 * 4)     // 67584
#define SMA_TOTAL (HSA_BYTES + WSL_BYTES + 512)
#define SMB_TOTAL (HS_BYTES + WSL_BYTES + 512)

// ---------------- mlp_a: acc1h = fp16(x @ W1[0:128] + ugb[batch])  (hidden under scatter) ----------------
__global__ void __launch_bounds__(512, 1) mlp_a_kernel(
    const float* __restrict__ x, const int* __restrict__ batch)
{
    extern __shared__ unsigned char sm[];
    unsigned* hs  = (unsigned*)sm;
    unsigned* wsl = (unsigned*)(sm + HSA_BYTES);
    int*      gb  = (int*)(sm + HSA_BYTES + WSL_BYTES);

    const int tid  = threadIdx.x;
    const int wid  = tid >> 5;
    const int lane = tid & 31;
    const int g    = lane >> 2;
    const int t    = lane & 3;
    const int base = blockIdx.x * 128;
    const int wm   = (wid >> 2) * 32;
    const int wn   = (wid & 3) * 64;

    {
#pragma unroll
        for (int i = 0; i < 2; i++) {
            int q = tid + i * 512;
            int n = q >> 2, j = q & 3;
            cp16((char*)wsl + n * 80 + j * 16, (const char*)g_W1t + n * 512 + j * 16);
        }
        CP_COMMIT();
    }

    if (tid < 128) {
        int node = min(base + tid, N_NODES - 1);
        gb[tid] = min(max(batch[node], 0), N_GRAPHS - 1);
    }

    // hs = fp16(x): 128 rows x 128 cols (float source)
#pragma unroll
    for (int i = 0; i < 8; i++) {
        int q = tid + i * 512;
        int r = q >> 5, c4 = (q & 31) << 2;
        int node = base + r;
        float4 v = make_float4(0.f, 0.f, 0.f, 0.f);
        if (node < N_NODES) v = __ldg((const float4*)(x + (size_t)node * 128 + c4));
        uint2 o; o.x = pack2(v.x, v.y); o.y = pack2(v.z, v.w);
        *(uint2*)(hs + r * HS2A + (c4 >> 1)) = o;
    }

    float acc[2][8][4];
#pragma unroll
    for (int a = 0; a < 2; a++)
#pragma unroll
        for (int b = 0; b < 8; b++)
#pragma unroll
            for (int q = 0; q < 4; q++) acc[a][b][q] = 0.f;

#pragma unroll 1
    for (int c = 0; c < 4; c++) {
        if (c < 3) {
            unsigned* dst = wsl + ((c + 1) & 1) * B1BUF;
            const char* src = (const char*)g_W1t + (c + 1) * 64;
#pragma unroll
            for (int i = 0; i < 2; i++) {
                int q = tid + i * 512;
                int n = q >> 2, j = q & 3;
                cp16((char*)dst + n * 80 + j * 16, src + n * 512 + j * 16);
            }
            CP_COMMIT(); CP_WAIT(1);
        } else {
            CP_WAIT(0);
        }
        __syncthreads();
        const unsigned* wb = wsl + (c & 1) * B1BUF;
#pragma unroll
        for (int ks = 0; ks < 2; ks++) {
            const int kg2 = c * 16 + ks * 8;
            const int kb2 = ks * 8;
            unsigned a_[2][4];
#pragma unroll
            for (int mf = 0; mf < 2; mf++) {
                int r0 = (wm + mf * 16 + g) * HS2A;
                int r1 = r0 + 8 * HS2A;
                a_[mf][0] = hs[r0 + kg2 + t];
                a_[mf][1] = hs[r1 + kg2 + t];
                a_[mf][2] = hs[r0 + kg2 + t + 4];
                a_[mf][3] = hs[r1 + kg2 + t + 4];
            }
#pragma unroll
            for (int nf = 0; nf < 8; nf++) {
                int n = wn + nf * 8 + g;
                unsigned b0 = wb[n * WSB + kb2 + t];
                unsigned b1 = wb[n * WSB + kb2 + t + 4];
#pragma unroll
                for (int mf = 0; mf < 2; mf++)
                    mma16(acc[mf][nf], a_[mf], b0, b1);
            }
        }
        __syncthreads();
    }

    // epilogue: acc1h = fp16(acc + ugb[batch])
#pragma unroll
    for (int mf = 0; mf < 2; mf++) {
        int r0 = wm + mf * 16 + g;
        int r1 = r0 + 8;
        int node0 = base + r0;
        int node1 = base + r1;
        const float* u0 = g_ugb + gb[r0] * 256;
        const float* u1 = g_ugb + gb[r1] * 256;
#pragma unroll
        for (int nf = 0; nf < 8; nf++) {
            int n0 = wn + nf * 8 + 2 * t;
            if (node0 < N_NODES)
                *(unsigned*)(g_acc1h + (size_t)node0 * 256 + n0) =
                    pack2(acc[mf][nf][0] + u0[n0], acc[mf][nf][1] + u0[n0 + 1]);
            if (node1 < N_NODES)
                *(unsigned*)(g_acc1h + (size_t)node1 * 256 + n0) =
                    pack2(acc[mf][nf][2] + u1[n0], acc[mf][nf][3] + u1[n0 + 1]);
        }
    }
}

// ---------------- mlp_b: h1 = relu(acc1h + aggh @ W1[128:256]); out = h1 @ W2 + b2 + x ----------------
__global__ void __launch_bounds__(512, 1) mlp_b_kernel(
    const float* __restrict__ x, const float* __restrict__ b2, float* __restrict__ out)
{
    extern __shared__ unsigned char sm[];
    unsigned* hs  = (unsigned*)sm;
    unsigned* wsl = (unsigned*)(sm + HS_BYTES);
    float*    b2s = (float*)(sm + HS_BYTES + WSL_BYTES);

    const int tid  = threadIdx.x;
    const int wid  = tid >> 5;
    const int lane = tid & 31;
    const int g    = lane >> 2;
    const int t    = lane & 3;
    const int base = blockIdx.x * 128;
    const int wm   = (wid >> 2) * 32;
    const int wn   = (wid & 3) * 64;

    {   // prefetch W1 agg-part chunk 0 (k 128..159)
#pragma unroll
        for (int i = 0; i < 2; i++) {
            int q = tid + i * 512;
            int n = q >> 2, j = q & 3;
            cp16((char*)wsl + n * 80 + j * 16, (const char*)g_W1t + 256 + n * 512 + j * 16);
        }
        CP_COMMIT();
    }

    if (tid < 128) b2s[tid] = b2[tid];

    // hs = aggh (fp16 source): 128 rows x 128 halves = 32 uint2 per row
#pragma unroll
    for (int i = 0; i < 8; i++) {
        int q = tid + i * 512;                 // 0..4095
        int r = q >> 5, u = q & 31;            // row, uint2-within-row
        int node = base + r;
        uint2 o = make_uint2(0u, 0u);
        if (node < N_NODES)
            o = __ldg((const uint2*)(g_aggh + (size_t)node * 128 + u * 4));
        *(uint2*)(hs + r * HS2 + u * 2) = o;
    }

    float acc[2][8][4];
#pragma unroll
    for (int a = 0; a < 2; a++)
#pragma unroll
        for (int b = 0; b < 8; b++)
#pragma unroll
            for (int q = 0; q < 4; q++) acc[a][b][q] = 0.f;

#pragma unroll 1
    for (int c = 0; c < 4; c++) {
        if (c < 3) {
            unsigned* dst = wsl + ((c + 1) & 1) * B1BUF;
            const char* src = (const char*)g_W1t + 256 + (c + 1) * 64;
#pragma unroll
            for (int i = 0; i < 2; i++) {
                int q = tid + i * 512;
                int n = q >> 2, j = q & 3;
                cp16((char*)dst + n * 80 + j * 16, src + n * 512 + j * 16);
            }
            CP_COMMIT(); CP_WAIT(1);
        } else {
            CP_WAIT(0);
        }
        __syncthreads();
        const unsigned* wb = wsl + (c & 1) * B1BUF;
#pragma unroll
        for (int ks = 0; ks < 2; ks++) {
            const int kg2 = c * 16 + ks * 8;
            const int kb2 = ks * 8;
            unsigned a_[2][4];
#pragma unroll
            for (int mf = 0; mf < 2; mf++) {
                int r0 = (wm + mf * 16 + g) * HS2;
                int r1 = r0 + 8 * HS2;
                a_[mf][0] = hs[r0 + kg2 + t];
                a_[mf][1] = hs[r1 + kg2 + t];
                a_[mf][2] = hs[r0 + kg2 + t + 4];
                a_[mf][3] = hs[r1 + kg2 + t + 4];
            }
#pragma unroll
            for (int nf = 0; nf < 8; nf++) {
                int n = wn + nf * 8 + g;
                unsigned b0 = wb[n * WSB + kb2 + t];
                unsigned b1 = wb[n * WSB + kb2 + t + 4];
#pragma unroll
                for (int mf = 0; mf < 2; mf++)
                    mma16(acc[mf][nf], a_[mf], b0, b1);
            }
        }
        __syncthreads();
    }

    {   // prefetch W2 chunk 0
        int n = tid >> 2, j = tid & 3;
        cp16((char*)wsl + n * 80 + j * 16, (const char*)g_W2t + n * 512 + j * 16);
        CP_COMMIT();
    }

    // epilogue 1: + acc1h (has ugb), relu, fp16 -> hs
#pragma unroll
    for (int mf = 0; mf < 2; mf++) {
        int r0 = wm + mf * 16 + g;
        int r1 = r0 + 8;
        int node0 = base + r0;
        int node1 = base + r1;
#pragma unroll
        for (int nf = 0; nf < 8; nf++) {
            int n0 = wn + nf * 8 + 2 * t;
            float2 a0 = make_float2(0.f, 0.f), a1 = make_float2(0.f, 0.f);
            if (node0 < N_NODES) {
                unsigned v = *(const unsigned*)(g_acc1h + (size_t)node0 * 256 + n0);
                __half2 h = *(__half2*)&v;
                a0 = __half22float2(h);
            }
            if (node1 < N_NODES) {
                unsigned v = *(const unsigned*)(g_acc1h + (size_t)node1 * 256 + n0);
                __half2 h = *(__half2*)&v;
                a1 = __half22float2(h);
            }
            float f0 = fmaxf(acc[mf][nf][0] + a0.x, 0.f);
            float f1 = fmaxf(acc[mf][nf][1] + a0.y, 0.f);
            float f2 = fmaxf(acc[mf][nf][2] + a1.x, 0.f);
            float f3 = fmaxf(acc[mf][nf][3] + a1.y, 0.f);
            hs[r0 * HS2 + (n0 >> 1)] = pack2(f0, f1);
            hs[r1 * HS2 + (n0 >> 1)] = pack2(f2, f3);
        }
    }
    __syncthreads();

    // GEMM2: [128,256]@[256,128]
    const int wn2 = (wid & 3) * 32;
    float acc2[2][4][4];
#pragma unroll
    for (int a = 0; a < 2; a++)
#pragma unroll
        for (int b = 0; b < 4; b++)
#pragma unroll
            for (int q = 0; q < 4; q++) acc2[a][b][q] = 0.f;

#pragma unroll 1
    for (int c = 0; c < 8; c++) {
        if (c < 7) {
            unsigned* dst = wsl + ((c + 1) & 1) * B2BUF;
            const char* src = (const char*)g_W2t + (c + 1) * 64;
            {
                int q = tid;
                int n = q >> 2, j = q & 3;
                cp16((char*)dst + n * 80 + j * 16, src + n * 512 + j * 16);
            }
            CP_COMMIT(); CP_WAIT(1);
        } else {
            CP_WAIT(0);
        }
        __syncthreads();
        const unsigned* wb = wsl + (c & 1) * B2BUF;
#pragma unroll
        for (int ks = 0; ks < 2; ks++) {
            const int kg2 = c * 16 + ks * 8;
            const int kb2 = ks * 8;
            unsigned a_[2][4];
#pragma unroll
            for (int mf = 0; mf < 2; mf++) {
                int r0 = (wm + mf * 16 + g) * HS2;
                int r1 = r0 + 8 * HS2;
                a_[mf][0] = hs[r0 + kg2 + t];
                a_[mf][1] = hs[r1 + kg2 + t];
                a_[mf][2] = hs[r0 + kg2 + t + 4];
                a_[mf][3] = hs[r1 + kg2 + t + 4];
            }
#pragma unroll
            for (int nf = 0; nf < 4; nf++) {
                int n = wn2 + nf * 8 + g;
                unsigned b0 = wb[n * WSB + kb2 + t];
                unsigned b1 = wb[n * WSB + kb2 + t + 4];
#pragma unroll
                for (int mf = 0; mf < 2; mf++)
                    mma16(acc2[mf][nf], a_[mf], b0, b1);
            }
        }
        __syncthreads();
    }

    // epilogue 2: + b2 + x residual -> out
#pragma unroll
    for (int mf = 0; mf < 2; mf++) {
        int r0 = wm + mf * 16 + g;
        int r1 = r0 + 8;
        int node0 = base + r0;
        int node1 = base + r1;
#pragma unroll
        for (int nf = 0; nf < 4; nf++) {
            int col = wn2 + nf * 8 + 2 * t;
            if (node0 < N_NODES) {
                float2 xv = *(const float2*)(x + (size_t)node0 * 128 + col);
                float2 o;
                o.x = acc2[mf][nf][0] + b2s[col] + xv.x;
                o.y = acc2[mf][nf][1] + b2s[col + 1] + xv.y;
                *(float2*)(out + (size_t)node0 * 128 + col) = o;
            }
            if (node1 < N_NODES) {
                float2 xv = *(const float2*)(x + (size_t)node1 * 128 + col);
                float2 o;
                o.x = acc2[mf][nf][2] + b2s[col] + xv.x;
                o.y = acc2[mf][nf][3] + b2s[col + 1] + xv.y;
                *(float2*)(out + (size_t)node1 * 128 + col) = o;
            }
        }
    }
}

// ---------------- launch: fork mlp_a under the scatter wall ----------------
extern "C" void kernel_launch(void* const* d_in, const int* in_sizes, int n_in,
                              void* d_out, int out_size) {
    const float* x = nullptr; const int* edge_index = nullptr; const float* edge_attr = nullptr;
    const float* u = nullptr; const int* batch = nullptr;
    const float* W1 = nullptr; const float* b1 = nullptr;
    const float* W2 = nullptr; const float* b2 = nullptr;

    for (int i = 0; i < n_in; i++) {
        switch (in_sizes[i]) {
            case 12800000:  x          = (const float*)d_in[i]; break;
            case 3200000:   edge_index = (const int*)d_in[i];   break;
            case 204800000: edge_attr  = (const float*)d_in[i]; break;
            case 1024:      u          = (const float*)d_in[i]; break;
            case 100000:    batch      = (const int*)d_in[i];   break;
            case 69632:     W1         = (const float*)d_in[i]; break;
            case 256:       b1         = (const float*)d_in[i]; break;
            case 32768:     W2         = (const float*)d_in[i]; break;
            case 128:       b2         = (const float*)d_in[i]; break;
            default: break;
        }
    }
    float* out = (float*)d_out;
    const int* col = edge_index + N_EDGES;

    cudaFuncSetAttribute(mlp_a_kernel, cudaFuncAttributeMaxDynamicSharedMemorySize, SMA_TOTAL);
    cudaFuncSetAttribute(mlp_b_kernel, cudaFuncAttributeMaxDynamicSharedMemorySize, SMB_TOTAL);

    void* agg_ptr = nullptr;
    cudaGetSymbolAddress(&agg_ptr, g_aggh);

    // bounded leak: kernel_launch runs only a handful of times
    cudaStream_t s2;
    cudaStreamCreateWithFlags(&s2, cudaStreamNonBlocking);
    cudaEvent_t e0, e2;
    cudaEventCreateWithFlags(&e0, cudaEventDisableTiming);
    cudaEventCreateWithFlags(&e2, cudaEventDisableTiming);

    cudaEventRecord(e0, 0);
    cudaStreamWaitEvent(s2, e0, 0);

    // s2: prep then x-part GEMM — fully hidden under memset+scatter
    prep_kernel<<<448, 256, 0, s2>>>(W1, W2, u, b1);
    mlp_a_kernel<<<(N_NODES + 127) / 128, 512, SMA_TOTAL, s2>>>(x, batch);
    cudaEventRecord(e2, s2);

    // main: zero fp16 agg, scatter (LSU-issue wall ~195us)
    // 4 edges per warp -> N_EDGES/32 blocks of 8 warps (R11-matched config).
    cudaMemsetAsync(agg_ptr, 0, (size_t)N_NODES * 128 * sizeof(__half));
    scatter_kernel<<<N_EDGES / 32, 256>>>(edge_attr, col);

    // join, then finish with the agg-half + GEMM2
    cudaStreamWaitEvent(0, e2, 0);
    mlp_b_kernel<<<(N_NODES + 127) / 128, 512, SMB_TOTAL>>>(x, b2, out);
}